// round 9
// baseline (speedup 1.0000x reference)
#include <cuda_runtime.h>

#define OUTB 7
#define NBINS 49
#define NCH 256
#define FH 50
#define FW 50
#define NPOS (FH * FW)        // 2500 positions per batch image
#define NROI 256
#define NEGV (-3e38f)
#define TILE_MAX 19           // Lh, Lw <= 19 for valid inputs (clamped)
#define PPAD 5120             // padded position count (2 batches * 2500 + slack)
#define STG_STRIDE 65         // staging row stride (odd-ish; see conflict note)

// Channel-last copy of features: g_featT[(b*2500 + h*50 + w) * 256 + c].
// 5.24 MB static device array (no dynamic allocation).
__device__ float g_featT[PPAD * NCH];

// ---- Kernel 1: transpose (b,c,h,w) -> (pos, c), both sides coalesced ----
__global__ void __launch_bounds__(256)
transpose_kernel(const float* __restrict__ feat) {
    __shared__ float t[32][33];
    const int p0 = blockIdx.x * 32;       // position group
    const int c0 = blockIdx.y * 32;       // channel group
    const int b  = blockIdx.z;
    const int tx = threadIdx.x;           // 32
    const int ty = threadIdx.y;           // 8

    #pragma unroll
    for (int dy = 0; dy < 4; dy++) {
        const int c = c0 + ty * 4 + dy;
        const int p = p0 + tx;
        float v = 0.0f;
        if (p < NPOS) v = __ldg(feat + ((size_t)(b * NCH + c)) * NPOS + p);
        t[ty * 4 + dy][tx] = v;           // row=c-local, col=p-local
    }
    __syncthreads();
    #pragma unroll
    for (int dy = 0; dy < 4; dy++) {
        const int p = p0 + ty * 4 + dy;
        const int c = c0 + tx;
        if (p < NPOS)
            g_featT[((size_t)(b * NPOS + p)) * NCH + c] = t[tx][ty * 4 + dy];
    }
}

// ---- Kernel 2: pooling straight from channel-last global, no input smem ----
// Block = (roi, 64-channel chunk); 4 warps; lane = 2 channels (float2).
__global__ void __launch_bounds__(128)
roipool_kernel(const float* __restrict__ rois,
               const int* __restrict__ raw,
               float* __restrict__ out) {
    __shared__ unsigned int binsS[NBINS];
    __shared__ float staging[NBINS * STG_STRIDE];   // [bin][ch], 12.7 KB

    const int tid  = threadIdx.x;
    const int warp = tid >> 5;
    const int lane = tid & 31;
    const int r  = blockIdx.x >> 2;       // 4 chunks per roi
    const int c0 = (blockIdx.x & 3) * 64;

    // Geometry (redundant per thread). Reference semantics: ri = int32(roi/16)
    // (fp32 mul, trunc); h-bounds from x coords, w-bounds from y coords.
    const float4 rv = __ldg(((const float4*)rois) + r);
    int x1 = (int)(rv.x * 0.0625f);
    int y1 = (int)(rv.y * 0.0625f);
    int x2 = (int)(rv.z * 0.0625f);
    int y2 = (int)(rv.w * 0.0625f);
    int Lh = x2 - x1;
    int Lw = y2 - y1;
    if (Lh < 0) Lh = 0; else if (Lh > TILE_MAX) Lh = TILE_MAX;
    if (Lw < 0) Lw = 0; else if (Lw > TILE_MAX) Lw = TILE_MAX;

    // Bin descriptors: start offset (within image, in positions), wh<=4, wn<=4.
    if (tid < NBINS) {
        const int ph = tid / OUTB;
        const int pw = tid - ph * OUTB;
        const int hs = (ph * Lh) / OUTB;
        const int he = ((ph + 1) * Lh + OUTB - 1) / OUTB;
        const int ws = (pw * Lw) / OUTB;
        const int we = ((pw + 1) * Lw + OUTB - 1) / OUTB;
        binsS[tid] = (unsigned int)((x1 + hs) * FW + (y1 + ws))
                   | ((unsigned int)(he - hs) << 16)
                   | ((unsigned int)(we - ws) << 20);
    }

    // int64-vs-int32 roi_indices detection: int64 LE values in {0,1} => all
    // 128 odd int32 words zero (prob ~2^-128 for random int32 {0,1} data).
    const int myok = (raw[2 * tid + 1] == 0);
    const int is64 = __syncthreads_and(myok);     // also publishes binsS
    const int b = is64 ? raw[2 * r] : raw[r];

    // ---- Bins: warp handles bb = warp, warp+4, ... (12-13 bins) ----
    // Per position: one LDG.64/lane, 256B contiguous per warp. Column loads
    // j=0..3 unconditional (address-safe: pos <= b*2500+48*50+51 < 5000),
    // accumulation predicated. Row loop bounded by true wh (h <= x2-1 <= 48).
    const float2* fT = (const float2*)g_featT;
    const int chBase = (c0 >> 1) + lane;          // float2 index of lane's channels
    for (int bb = warp; bb < NBINS; bb += 4) {
        const unsigned int e = binsS[bb];
        const int wh = (e >> 16) & 0xF;
        const int wn = e >> 20;
        const float2* p = fT + ((size_t)(b * NPOS + (int)(e & 0xFFFF))) * (NCH / 2)
                        + chBase;
        float2 m = make_float2(NEGV, NEGV);
        for (int i = 0; i < wh; i++) {
            float2 v0 = __ldg(p);
            float2 v1 = __ldg(p + (NCH / 2));
            float2 v2 = __ldg(p + 2 * (NCH / 2));
            float2 v3 = __ldg(p + 3 * (NCH / 2));
            m.x = fmaxf(m.x, v0.x);  m.y = fmaxf(m.y, v0.y);   // wn >= 1 always
            if (wn > 1) { m.x = fmaxf(m.x, v1.x);  m.y = fmaxf(m.y, v1.y); }
            if (wn > 2) { m.x = fmaxf(m.x, v2.x);  m.y = fmaxf(m.y, v2.y); }
            if (wn > 3) { m.x = fmaxf(m.x, v3.x);  m.y = fmaxf(m.y, v3.y); }
            p += FW * (NCH / 2);
        }
        staging[bb * STG_STRIDE + 2 * lane]     = m.x;
        staging[bb * STG_STRIDE + 2 * lane + 1] = m.y;
    }
    __syncthreads();

    // ---- Coalesced output: 3136 contiguous floats for (r, c0..c0+63) ----
    // k = ch*49 + bb matches the global layout; staging read is spread across
    // banks by the odd 65 stride.
    float* o = out + ((size_t)r * NCH + c0) * NBINS;
    for (int k = tid; k < 64 * NBINS; k += 128) {
        const int ch = k / NBINS;                  // const divisor -> mul.hi
        const int bb = k - ch * NBINS;
        o[k] = staging[bb * STG_STRIDE + ch];
    }
}

extern "C" void kernel_launch(void* const* d_in, const int* in_sizes, int n_in,
                              void* d_out, int out_size) {
    const float* features = (const float*)d_in[0];
    const float* rois     = (const float*)d_in[1];
    const int*   roi_idx  = (const int*)d_in[2];  // width detected at runtime
    float* out = (float*)d_out;

    dim3 tgrid((NPOS + 31) / 32, NCH / 32, 2);    // 79 x 8 x 2 = 1264 blocks
    transpose_kernel<<<tgrid, dim3(32, 8)>>>(features);

    roipool_kernel<<<NROI * 4, 128>>>(rois, roi_idx, out);
}

// round 10
// speedup vs baseline: 1.7175x; 1.7175x over previous
#include <cuda_runtime.h>

#define OUTB 7
#define NBINS 49
#define NCH 256
#define FH 50
#define FW 50
#define NPOS (FH * FW)        // 2500 positions per batch image
#define NROI 256
#define NEGV (-3e38f)
#define TILE_MAX 19           // Lh, Lw <= 19 for valid inputs (clamped)
#define PPAD 5120             // padded position count (2*2500 + overread slack)
#define STG_STRIDE 65         // staging row stride (odd => conflict-free)
#define CH2 (NCH / 2)         // float2 stride per position

// Channel-last copy of features: g_featT[(b*2500 + h*50 + w) * 256 + c].
__device__ float g_featT[PPAD * NCH];

// ---- Kernel 1: transpose (b,c,h,w) -> (pos, c), both sides coalesced ----
__global__ void __launch_bounds__(256)
transpose_kernel(const float* __restrict__ feat) {
    __shared__ float t[32][33];
    const int p0 = blockIdx.x * 32;
    const int c0 = blockIdx.y * 32;
    const int b  = blockIdx.z;
    const int tx = threadIdx.x;           // 32
    const int ty = threadIdx.y;           // 8

    #pragma unroll
    for (int dy = 0; dy < 4; dy++) {
        const int c = c0 + ty * 4 + dy;
        const int p = p0 + tx;
        float v = 0.0f;
        if (p < NPOS) v = __ldg(feat + ((size_t)(b * NCH + c)) * NPOS + p);
        t[ty * 4 + dy][tx] = v;
    }
    __syncthreads();
    #pragma unroll
    for (int dy = 0; dy < 4; dy++) {
        const int p = p0 + ty * 4 + dy;
        const int c = c0 + tx;
        if (p < NPOS)
            g_featT[((size_t)(b * NPOS + p)) * NCH + c] = t[tx][ty * 4 + dy];
    }
}

// ---- Kernel 2: pool from channel-last global; whole-window MLP per bin ----
// Block = (roi, 64-ch chunk), 8 warps; warp owns bins warp, warp+8, ...
__global__ void __launch_bounds__(256)
roipool_kernel(const float* __restrict__ rois,
               const int* __restrict__ raw,
               float* __restrict__ out) {
    __shared__ unsigned int binsS[NBINS];
    __shared__ float staging[NBINS * STG_STRIDE];   // [bin][ch], 12.7 KB

    const int tid  = threadIdx.x;
    const int warp = tid >> 5;
    const int lane = tid & 31;
    const int r  = blockIdx.x >> 2;       // 4 chunks per roi
    const int c0 = (blockIdx.x & 3) * 64;

    // Geometry (redundant per thread). Reference semantics: ri = int32(roi/16)
    // (fp32 mul, trunc); h-bounds from x coords, w-bounds from y coords.
    const float4 rv = __ldg(((const float4*)rois) + r);
    int x1 = (int)(rv.x * 0.0625f);
    int y1 = (int)(rv.y * 0.0625f);
    int x2 = (int)(rv.z * 0.0625f);
    int y2 = (int)(rv.w * 0.0625f);
    int Lh = x2 - x1;
    int Lw = y2 - y1;
    if (Lh < 0) Lh = 0; else if (Lh > TILE_MAX) Lh = TILE_MAX;
    if (Lw < 0) Lw = 0; else if (Lw > TILE_MAX) Lw = TILE_MAX;

    // Bin descriptors: image-pos of window start, wh<=4, wn<=4.
    if (tid < NBINS) {
        const int ph = tid / OUTB;
        const int pw = tid - ph * OUTB;
        const int hs = (ph * Lh) / OUTB;
        const int he = ((ph + 1) * Lh + OUTB - 1) / OUTB;
        const int ws = (pw * Lw) / OUTB;
        const int we = ((pw + 1) * Lw + OUTB - 1) / OUTB;
        binsS[tid] = (unsigned int)((x1 + hs) * FW + (y1 + ws))
                   | ((unsigned int)(he - hs) << 16)
                   | ((unsigned int)(we - ws) << 20);
    }

    // int64-vs-int32 roi_indices detection: int64 LE values in {0,1} => all
    // odd int32 words zero (prob ~2^-128 for random int32 {0,1} data).
    const int myok = (tid < NROI / 2) ? (raw[2 * tid + 1] == 0) : 1;
    const int is64 = __syncthreads_and(myok);     // also publishes binsS
    const int b = is64 ? raw[2 * r] : raw[r];

    const float2* fT = (const float2*)g_featT;
    const int chBase = (c0 >> 1) + lane;

    for (int bb = warp; bb < NBINS; bb += 8) {
        const unsigned int e = binsS[bb];
        const int wh = (e >> 16) & 0xF;
        const int wn = e >> 20;
        const float2* p = fT + ((size_t)(b * NPOS + (int)(e & 0xFFFF))) * CH2
                        + chBase;

        // Hoist ALL window loads first: up to 16 independent LDG.64 in flight.
        // Row gate is warp-uniform; columns unconditional (address-safe:
        // rows only when i<wh => h<=x2-1<=48; w<=y1+ws+3<=50 => pos<=4950<5120).
        float2 v[4][4];
        #pragma unroll
        for (int i = 0; i < 4; i++) {
            if (i < wh) {
                const float2* q = p + i * (FW * CH2);
                v[i][0] = __ldg(q);
                v[i][1] = __ldg(q + CH2);
                v[i][2] = __ldg(q + 2 * CH2);
                v[i][3] = __ldg(q + 3 * CH2);
            } else {
                v[i][0] = v[i][1] = v[i][2] = v[i][3] = make_float2(NEGV, NEGV);
            }
        }

        // Column-wise max across rows, then uniform wn masking.
        float2 col[4];
        #pragma unroll
        for (int j = 0; j < 4; j++) {
            float2 cmax = v[0][j];
            #pragma unroll
            for (int i = 1; i < 4; i++) {
                cmax.x = fmaxf(cmax.x, v[i][j].x);
                cmax.y = fmaxf(cmax.y, v[i][j].y);
            }
            col[j] = cmax;
        }
        float2 m = col[0];                               // wn >= 1 always
        if (wn > 1) { m.x = fmaxf(m.x, col[1].x); m.y = fmaxf(m.y, col[1].y); }
        if (wn > 2) { m.x = fmaxf(m.x, col[2].x); m.y = fmaxf(m.y, col[2].y); }
        if (wn > 3) { m.x = fmaxf(m.x, col[3].x); m.y = fmaxf(m.y, col[3].y); }

        staging[bb * STG_STRIDE + 2 * lane]     = m.x;
        staging[bb * STG_STRIDE + 2 * lane + 1] = m.y;
    }
    __syncthreads();

    // ---- Coalesced output: 3136 contiguous floats for (r, c0..c0+63) ----
    float* o = out + ((size_t)r * NCH + c0) * NBINS;
    for (int k = tid; k < 64 * NBINS; k += 256) {
        const int ch = k / NBINS;                        // const div -> mul.hi
        const int bbq = k - ch * NBINS;
        o[k] = staging[bbq * STG_STRIDE + ch];
    }
}

extern "C" void kernel_launch(void* const* d_in, const int* in_sizes, int n_in,
                              void* d_out, int out_size) {
    const float* features = (const float*)d_in[0];
    const float* rois     = (const float*)d_in[1];
    const int*   roi_idx  = (const int*)d_in[2];  // width detected at runtime
    float* out = (float*)d_out;

    dim3 tgrid((NPOS + 31) / 32, NCH / 32, 2);    // 79 x 8 x 2
    transpose_kernel<<<tgrid, dim3(32, 8)>>>(features);

    roipool_kernel<<<NROI * 4, 256>>>(rois, roi_idx, out);
}